// round 6
// baseline (speedup 1.0000x reference)
#include <cuda_runtime.h>

// Causal depthwise conv1d (K=4) + SiLU, fp32, layout (B, L, D) with D contiguous.
// out[b,l,d] = silu( sum_{k=0..3} x[b, l-3+k, d] * w[d, k] )   (zero pad l<0)
//
// Strategy: HBM-bound streaming kernel.
//  - float4 vectorization across D (contiguous dim) -> coalesced 16B/thread.
//  - Each thread owns one (b, d4) column, streams CHUNK=16 consecutive l with a
//    3-deep register sliding window: 19 loads per 16 outputs (1.19x read amp).
//  - Weights: one float4 per channel (K=4 contiguous) -> 4 float4 loads/thread.

#define CONV_K 4
#define CHUNK 16

__device__ __forceinline__ float silu_f(float v) {
    // x * sigmoid(x) = x / (1 + e^-x). Fast intrinsics: ~2 MUFU/elem; rel err
    // well under the 1e-3 bench threshold.
    return v * __frcp_rn(1.0f + __expf(-v));
}

__global__ __launch_bounds__(256, 4)
void causal_dwconv_silu_kernel(const float4* __restrict__ x,
                               const float4* __restrict__ w4,  // w4[d] = {w[d,0..3]}
                               float4* __restrict__ y,
                               int L, int Dv, int chunks_per_batch) {
    int t = blockIdx.x * blockDim.x + threadIdx.x;
    int dv   = t % Dv;                       // float4 index along D (consecutive per warp)
    int rest = t / Dv;
    int lc   = rest % chunks_per_batch;      // which 16-row chunk of L
    int b    = rest / chunks_per_batch;

    int l0 = lc * CHUNK;

    // Per-channel weights for the 4 packed channels d = 4*dv + j.
    const float4 wA = w4[4 * dv + 0];
    const float4 wB = w4[4 * dv + 1];
    const float4 wC = w4[4 * dv + 2];
    const float4 wD = w4[4 * dv + 3];

    long base = (long)b * L * Dv + dv;       // float4 index of (b, l=0, dv)
    const float4* xp = x + base;
    float4*       yp = y + base;

    // Sliding-window history: h0 = x[l-3], h1 = x[l-2], h2 = x[l-1].
    float4 h0, h1, h2;
    if (l0 == 0) {
        h0 = make_float4(0.f, 0.f, 0.f, 0.f);
        h1 = h0;
        h2 = h0;
    } else {
        h0 = __ldg(&xp[(long)(l0 - 3) * Dv]);
        h1 = __ldg(&xp[(long)(l0 - 2) * Dv]);
        h2 = __ldg(&xp[(long)(l0 - 1) * Dv]);
    }

    const float4* px = xp + (long)l0 * Dv;
    float4*       py = yp + (long)l0 * Dv;

#pragma unroll
    for (int i = 0; i < CHUNK; ++i) {
        float4 c = __ldg(&px[(long)i * Dv]);

        float4 o;
        o.x = fmaf(h0.x, wA.x, fmaf(h1.x, wA.y, fmaf(h2.x, wA.z, c.x * wA.w)));
        o.y = fmaf(h0.y, wB.x, fmaf(h1.y, wB.y, fmaf(h2.y, wB.z, c.y * wB.w)));
        o.z = fmaf(h0.z, wC.x, fmaf(h1.z, wC.y, fmaf(h2.z, wC.z, c.z * wC.w)));
        o.w = fmaf(h0.w, wD.x, fmaf(h1.w, wD.y, fmaf(h2.w, wD.z, c.w * wD.w)));

        o.x = silu_f(o.x);
        o.y = silu_f(o.y);
        o.z = silu_f(o.z);
        o.w = silu_f(o.w);

        py[(long)i * Dv] = o;

        h0 = h1; h1 = h2; h2 = c;
    }
}

extern "C" void kernel_launch(void* const* d_in, const int* in_sizes, int n_in,
                              void* d_out, int out_size) {
    const float4* x  = (const float4*)d_in[0];   // inputs (B, L, D) fp32
    const float4* w4 = (const float4*)d_in[1];   // weight (D, 1, K=4) fp32 -> float4 per d
    float4* y = (float4*)d_out;

    const int D  = in_sizes[1] / CONV_K;         // 2048
    const int Dv = D / 4;                        // 512 float4 per row
    const int L  = 4096;                         // reference shape
    const int B  = in_sizes[0] / (L * D);        // 4
    const int chunks_per_batch = L / CHUNK;      // 256

    const long total_threads = (long)B * chunks_per_batch * Dv;  // 524288
    const int  threads = 256;
    const int  blocks  = (int)((total_threads + threads - 1) / threads);

    causal_dwconv_silu_kernel<<<blocks, threads>>>(x, w4, y, L, Dv, chunks_per_batch);
}

// round 7
// speedup vs baseline: 1.3126x; 1.3126x over previous
#include <cuda_runtime.h>

// Causal depthwise conv1d (K=4) + SiLU, fp32, layout (B, L, D), D contiguous.
// out[b,l,d] = silu( sum_{k=0..3} x[b, l-3+k, d] * w[d, k] )   (zero pad l<0)
//
// R6: latency-bound fix. Explicit front-batched load phase (11 predicated LDG.128
// into a register array -> MLP_p1 = 11) before any compute, CHUNK=8, streaming
// stores (__stcs). Traffic: 1.375x read amp + 1x write = ~318 MB.

#define CONV_K 4
#define CHUNK 8                      // outputs per thread along L
#define NLOAD (CHUNK + CONV_K - 1)   // 11 input rows per thread

__device__ __forceinline__ float silu_f(float v) {
    return v * __frcp_rn(1.0f + __expf(-v));
}

__global__ __launch_bounds__(256, 3)
void causal_dwconv_silu_kernel(const float4* __restrict__ x,
                               const float4* __restrict__ w4,  // w4[d] = {w[d,0..3]}
                               float4* __restrict__ y,
                               int L, int Dv, int chunks_per_batch) {
    int t = blockIdx.x * blockDim.x + threadIdx.x;
    int dv   = t % Dv;                       // float4 index along D (consecutive per warp)
    int rest = t / Dv;
    int lc   = rest % chunks_per_batch;      // which CHUNK-row slab of L
    int b    = rest / chunks_per_batch;

    const int l0 = lc * CHUNK;

    const long base = (long)b * L * Dv + dv;     // float4 index of (b, l=0, dv)
    const float4* xp = x + base;
    float4*       yp = y + base;

    // ---- Phase 1: front-batched loads (MLP_p1 = 11) ----
    float4 v[NLOAD];
    const float4 Z = make_float4(0.f, 0.f, 0.f, 0.f);
#pragma unroll
    for (int i = 0; i < NLOAD; ++i) {
        int l = l0 - 3 + i;                  // only l0==0 chunk has l<0 (predicated)
        v[i] = (l >= 0) ? __ldg(&xp[(long)l * Dv]) : Z;
    }

    // Weights for the 4 packed channels d = 4*dv + j (one float4 each, K=4).
    const float4 wA = __ldg(&w4[4 * dv + 0]);
    const float4 wB = __ldg(&w4[4 * dv + 1]);
    const float4 wC = __ldg(&w4[4 * dv + 2]);
    const float4 wD = __ldg(&w4[4 * dv + 3]);

    // ---- Phase 2: compute + streaming stores ----
    float4* py = yp + (long)l0 * Dv;
#pragma unroll
    for (int i = 0; i < CHUNK; ++i) {
        const float4 a0 = v[i], a1 = v[i + 1], a2 = v[i + 2], a3 = v[i + 3];
        float4 o;
        o.x = fmaf(a0.x, wA.x, fmaf(a1.x, wA.y, fmaf(a2.x, wA.z, a3.x * wA.w)));
        o.y = fmaf(a0.y, wB.x, fmaf(a1.y, wB.y, fmaf(a2.y, wB.z, a3.y * wB.w)));
        o.z = fmaf(a0.z, wC.x, fmaf(a1.z, wC.y, fmaf(a2.z, wC.z, a3.z * wC.w)));
        o.w = fmaf(a0.w, wD.x, fmaf(a1.w, wD.y, fmaf(a2.w, wD.z, a3.w * wD.w)));

        o.x = silu_f(o.x);
        o.y = silu_f(o.y);
        o.z = silu_f(o.z);
        o.w = silu_f(o.w);

        __stcs(&py[(long)i * Dv], o);        // streaming: output never re-read
    }
}

extern "C" void kernel_launch(void* const* d_in, const int* in_sizes, int n_in,
                              void* d_out, int out_size) {
    const float4* x  = (const float4*)d_in[0];   // inputs (B, L, D) fp32
    const float4* w4 = (const float4*)d_in[1];   // weight (D, 1, K=4) fp32
    float4* y = (float4*)d_out;

    const int D  = in_sizes[1] / CONV_K;         // 2048
    const int Dv = D / 4;                        // 512
    const int L  = 4096;
    const int B  = in_sizes[0] / (L * D);        // 4
    const int chunks_per_batch = L / CHUNK;      // 512

    const long total_threads = (long)B * chunks_per_batch * Dv;  // 1,048,576
    const int  threads = 256;
    const int  blocks  = (int)((total_threads + threads - 1) / threads);

    causal_dwconv_silu_kernel<<<blocks, threads>>>(x, w4, y, L, Dv, chunks_per_batch);
}

// round 8
// speedup vs baseline: 1.3596x; 1.0358x over previous
#include <cuda_runtime.h>
#include <cstdint>

// Causal depthwise conv1d (K=4) + SiLU, fp32, (B, L, D) with D contiguous.
// R7: instruction diet. Compile-time shape constants -> LDG/STG with immediate
// offsets (no per-access IMAD.WIDE), 32-bit indexing, packed fma.rn.f32x2 for
// the conv taps (16 FFMA -> 8 FFMA2 per float4 output). Memory structure from
// R6 kept: front-batched 11x LDG.128 (MLP_p1=11), streaming stores.

#define CONV_K 4
#define CHUNK  8
#define NLOAD  (CHUNK + CONV_K - 1)   // 11

// Fixed problem shape (reference: B=4, L=4096, D=2048)
#define C_L   4096
#define C_D   2048
#define C_DV  (C_D / 4)               // 512 float4 per row
#define C_CPB (C_L / CHUNK)           // 512 chunks per batch

__device__ __forceinline__ float silu_f(float v) {
    return v * __frcp_rn(1.0f + __expf(-v));
}

__device__ __forceinline__ uint64_t pack2(float lo, float hi) {
    uint64_t r;
    asm("mov.b64 %0, {%1, %2};" : "=l"(r) : "f"(lo), "f"(hi));
    return r;
}
__device__ __forceinline__ void unpack2(uint64_t v, float& lo, float& hi) {
    asm("mov.b64 {%0, %1}, %2;" : "=f"(lo), "=f"(hi) : "l"(v));
}
__device__ __forceinline__ uint64_t fma2(uint64_t a, uint64_t b, uint64_t c) {
    uint64_t d;
    asm("fma.rn.f32x2 %0, %1, %2, %3;" : "=l"(d) : "l"(a), "l"(b), "l"(c));
    return d;
}
__device__ __forceinline__ uint64_t mul2(uint64_t a, uint64_t b) {
    uint64_t d;
    asm("mul.rn.f32x2 %0, %1, %2;" : "=l"(d) : "l"(a), "l"(b));
    return d;
}

__global__ __launch_bounds__(256, 3)
void causal_dwconv_silu_kernel(const float4* __restrict__ x,
                               const float4* __restrict__ w4,
                               float4* __restrict__ y) {
    const unsigned t = blockIdx.x * 256u + threadIdx.x;
    const unsigned dv   = t & (C_DV - 1);          // t % 512
    const unsigned rest = t >> 9;                  // t / 512
    const unsigned lc   = rest & (C_CPB - 1);      // rest % 512
    const unsigned b    = rest >> 9;               // rest / 512

    const unsigned l0   = lc * CHUNK;
    const unsigned base = b * (C_L * C_DV) + l0 * C_DV + dv;  // float4 idx of (b,l0,dv)

    const float4* px = x + base;                   // points at l0; halo at negative offsets
    float4*       py = y + base;

    // ---- Phase 1: front-batched loads (MLP_p1 = 11), immediate offsets ----
    float4 v[NLOAD];
    const float4 Z = make_float4(0.f, 0.f, 0.f, 0.f);
    if (l0 == 0) {
        v[0] = Z; v[1] = Z; v[2] = Z;
#pragma unroll
        for (int i = 3; i < NLOAD; ++i) v[i] = __ldg(&px[(i - 3) * C_DV]);
    } else {
#pragma unroll
        for (int i = 0; i < NLOAD; ++i) v[i] = __ldg(&px[(i - 3) * C_DV]);
    }

    // Weights for channels d = 4*dv + {0,1,2,3}; repack per-tap as f32x2 pairs.
    const float4 wA = __ldg(&w4[4 * dv + 0]);
    const float4 wB = __ldg(&w4[4 * dv + 1]);
    const float4 wC = __ldg(&w4[4 * dv + 2]);
    const float4 wD = __ldg(&w4[4 * dv + 3]);
    const uint64_t wxy0 = pack2(wA.x, wB.x), wxy1 = pack2(wA.y, wB.y),
                   wxy2 = pack2(wA.z, wB.z), wxy3 = pack2(wA.w, wB.w);
    const uint64_t wzw0 = pack2(wC.x, wD.x), wzw1 = pack2(wC.y, wD.y),
                   wzw2 = pack2(wC.z, wD.z), wzw3 = pack2(wC.w, wD.w);

    // ---- Phase 2: packed-FMA compute + streaming stores ----
#pragma unroll
    for (int i = 0; i < CHUNK; ++i) {
        const float4 a0 = v[i], a1 = v[i + 1], a2 = v[i + 2], a3 = v[i + 3];

        uint64_t pxy = mul2(pack2(a3.x, a3.y), wxy3);
        pxy = fma2(pack2(a2.x, a2.y), wxy2, pxy);
        pxy = fma2(pack2(a1.x, a1.y), wxy1, pxy);
        pxy = fma2(pack2(a0.x, a0.y), wxy0, pxy);

        uint64_t pzw = mul2(pack2(a3.z, a3.w), wzw3);
        pzw = fma2(pack2(a2.z, a2.w), wzw2, pzw);
        pzw = fma2(pack2(a1.z, a1.w), wzw1, pzw);
        pzw = fma2(pack2(a0.z, a0.w), wzw0, pzw);

        float4 o;
        unpack2(pxy, o.x, o.y);
        unpack2(pzw, o.z, o.w);

        o.x = silu_f(o.x);
        o.y = silu_f(o.y);
        o.z = silu_f(o.z);
        o.w = silu_f(o.w);

        __stcs(&py[i * C_DV], o);
    }
}

extern "C" void kernel_launch(void* const* d_in, const int* in_sizes, int n_in,
                              void* d_out, int out_size) {
    const float4* x  = (const float4*)d_in[0];
    const float4* w4 = (const float4*)d_in[1];
    float4* y = (float4*)d_out;

    const int B = in_sizes[0] / (C_L * C_D);                   // 4
    const long total_threads = (long)B * C_CPB * C_DV;         // 1,048,576
    const int blocks = (int)(total_threads / 256);

    causal_dwconv_silu_kernel<<<blocks, 256>>>(x, w4, y);
}

// round 9
// speedup vs baseline: 1.3720x; 1.0092x over previous
#include <cuda_runtime.h>

// Causal depthwise conv1d (K=4) + SiLU, fp32, (B, L, D), D contiguous.
// R8: phase-bubble fix via finer-grained CTAs + higher occupancy.
//  - CHUNK=4 (NLOAD=7 front-batched LDG.128), scalar FFMA (f32x2 reverted:
//    pack/unpack MOVs land on ALU pipe and cancel the FFMA savings).
//  - __launch_bounds__(256,4): 32 resident warps/SM, 8192 CTAs -> load phases
//    of some CTAs overlap compute/store phases of others -> DRAM stays fed.
//  - Halo reads (3 of 7 rows) are concurrently fetched by neighbor CTAs -> L2 hits.

#define CONV_K 4
#define CHUNK  4
#define NLOAD  (CHUNK + CONV_K - 1)   // 7

// Fixed problem shape (reference: B=4, L=4096, D=2048)
#define C_L   4096
#define C_D   2048
#define C_DV  (C_D / 4)               // 512 float4 per row
#define C_CPB (C_L / CHUNK)           // 1024 chunks per batch

__device__ __forceinline__ float silu_f(float v) {
    return v * __frcp_rn(1.0f + __expf(-v));
}

__global__ __launch_bounds__(256, 4)
void causal_dwconv_silu_kernel(const float4* __restrict__ x,
                               const float4* __restrict__ w4,
                               float4* __restrict__ y) {
    const unsigned t = blockIdx.x * 256u + threadIdx.x;
    const unsigned dv   = t & (C_DV - 1);           // t % 512
    const unsigned rest = t >> 9;                   // t / 512
    const unsigned lc   = rest & (C_CPB - 1);       // rest % 1024
    const unsigned b    = rest >> 10;               // rest / 1024

    const unsigned l0   = lc * CHUNK;
    const unsigned base = b * (C_L * C_DV) + l0 * C_DV + dv;

    const float4* px = x + base;                    // (b, l0, dv); halo at negative offsets
    float4*       py = y + base;

    // ---- Phase 1: front-batched loads (MLP_p1 = 7), immediate offsets ----
    float4 v[NLOAD];
    const float4 Z = make_float4(0.f, 0.f, 0.f, 0.f);
    if (l0 == 0) {
        v[0] = Z; v[1] = Z; v[2] = Z;
#pragma unroll
        for (int i = 3; i < NLOAD; ++i) v[i] = __ldg(&px[(i - 3) * C_DV]);
    } else {
#pragma unroll
        for (int i = 0; i < NLOAD; ++i) v[i] = __ldg(&px[(i - 3) * C_DV]);
    }

    // Weights for channels d = 4*dv + {0,1,2,3}.
    const float4 wA = __ldg(&w4[4 * dv + 0]);
    const float4 wB = __ldg(&w4[4 * dv + 1]);
    const float4 wC = __ldg(&w4[4 * dv + 2]);
    const float4 wD = __ldg(&w4[4 * dv + 3]);

    // ---- Phase 2: compute + streaming stores ----
#pragma unroll
    for (int i = 0; i < CHUNK; ++i) {
        const float4 a0 = v[i], a1 = v[i + 1], a2 = v[i + 2], a3 = v[i + 3];
        float4 o;
        o.x = fmaf(a0.x, wA.x, fmaf(a1.x, wA.y, fmaf(a2.x, wA.z, a3.x * wA.w)));
        o.y = fmaf(a0.y, wB.x, fmaf(a1.y, wB.y, fmaf(a2.y, wB.z, a3.y * wB.w)));
        o.z = fmaf(a0.z, wC.x, fmaf(a1.z, wC.y, fmaf(a2.z, wC.z, a3.z * wC.w)));
        o.w = fmaf(a0.w, wD.x, fmaf(a1.w, wD.y, fmaf(a2.w, wD.z, a3.w * wD.w)));

        o.x = silu_f(o.x);
        o.y = silu_f(o.y);
        o.z = silu_f(o.z);
        o.w = silu_f(o.w);

        __stcs(&py[i * C_DV], o);
    }
}

extern "C" void kernel_launch(void* const* d_in, const int* in_sizes, int n_in,
                              void* d_out, int out_size) {
    const float4* x  = (const float4*)d_in[0];
    const float4* w4 = (const float4*)d_in[1];
    float4* y = (float4*)d_out;

    const int B = in_sizes[0] / (C_L * C_D);                   // 4
    const long total_threads = (long)B * C_CPB * C_DV;         // 2,097,152
    const int blocks = (int)(total_threads / 256);             // 8192

    causal_dwconv_silu_kernel<<<blocks, 256>>>(x, w4, y);
}

// round 10
// speedup vs baseline: 1.3977x; 1.0187x over previous
#include <cuda_runtime.h>

// Causal depthwise conv1d (K=4) + SiLU, fp32, (B, L, D), D contiguous.
// R9: continuous-stream kernel. Each thread owns S=32 consecutive l in one
// (b, dv) column, with an 8-deep float4 register ring + prefetch distance 5.
// Steady state issues exactly 1 LDG.128 + 1 STG.128 per output (1.09x issued
// read amp incl. prologue, vs 1.75x in R8) -> homogeneous load stream, no
// phase bubbles, minimal L1tex wavefront pressure.

#define CONV_K 4
#define S      32                    // outputs per thread along L
#define RING   8                     // register ring depth (float4 rows)

// Fixed problem shape (reference: B=4, L=4096, D=2048)
#define C_L   4096
#define C_D   2048
#define C_DV  (C_D / 4)              // 512 float4 per row
#define C_SPB (C_L / S)              // 128 spans per (batch, column)

__device__ __forceinline__ float silu_f(float v) {
    // MUFU.EX2 + MUFU.RCP path; no Newton refinement (__fdividef).
    return __fdividef(v, 1.0f + __expf(-v));
}

__global__ __launch_bounds__(256, 3)
void causal_dwconv_silu_kernel(const float4* __restrict__ x,
                               const float4* __restrict__ w4,
                               float4* __restrict__ y) {
    const unsigned t = blockIdx.x * 256u + threadIdx.x;
    const unsigned dv   = t & (C_DV - 1);           // t % 512
    const unsigned rest = t >> 9;                   // t / 512  (CTA-uniform)
    const unsigned sp   = rest & (C_SPB - 1);       // span index within column
    const unsigned b    = rest >> 7;                // rest / 128

    const unsigned l0   = sp * S;
    const unsigned base = b * (C_L * C_DV) + l0 * C_DV + dv;

    const float4* px = x + base;                    // (b, l0, dv); halo at negative offs
    float4*       py = y + base;

    // Weights for channels d = 4*dv + {0..3} (one float4 each).
    const float4 wA = __ldg(&w4[4 * dv + 0]);
    const float4 wB = __ldg(&w4[4 * dv + 1]);
    const float4 wC = __ldg(&w4[4 * dv + 2]);
    const float4 wD = __ldg(&w4[4 * dv + 3]);

    // ---- Prologue: fill ring with rows l0-3 .. l0+4 (front-batched, MLP=8) ----
    // v[j] holds row l0 - 3 + j  (mod-RING rotation thereafter).
    float4 v[RING];
    const float4 Z = make_float4(0.f, 0.f, 0.f, 0.f);
    if (l0 == 0) {                                  // CTA-uniform branch
        v[0] = Z; v[1] = Z; v[2] = Z;
#pragma unroll
        for (int j = 3; j < RING; ++j) v[j] = __ldg(&px[(j - 3) * C_DV]);
    } else {
#pragma unroll
        for (int j = 0; j < RING; ++j) v[j] = __ldg(&px[(j - 3) * C_DV]);
    }

    // ---- Steady stream: per output, 1 prefetch + 16 FFMA + SiLU + 1 store ----
    // Output i consumes ring slots (i..i+3)&7 (rows l0-3+i .. l0+i); slot i&7 is
    // then dead and is refilled with row l0+i+5 (prefetch distance RING).
#pragma unroll
    for (int i = 0; i < S; ++i) {
        const float4 a0 = v[(i + 0) & (RING - 1)];
        const float4 a1 = v[(i + 1) & (RING - 1)];
        const float4 a2 = v[(i + 2) & (RING - 1)];
        const float4 a3 = v[(i + 3) & (RING - 1)];

        // Prefetch (compile-time suppressed near span end: row must be < l0+S).
        if (i + 5 < S) {
            v[i & (RING - 1)] = __ldg(&px[(i + 5) * C_DV]);
        }

        float4 o;
        o.x = fmaf(a0.x, wA.x, fmaf(a1.x, wA.y, fmaf(a2.x, wA.z, a3.x * wA.w)));
        o.y = fmaf(a0.y, wB.x, fmaf(a1.y, wB.y, fmaf(a2.y, wB.z, a3.y * wB.w)));
        o.z = fmaf(a0.z, wC.x, fmaf(a1.z, wC.y, fmaf(a2.z, wC.z, a3.z * wC.w)));
        o.w = fmaf(a0.w, wD.x, fmaf(a1.w, wD.y, fmaf(a2.w, wD.z, a3.w * wD.w)));

        o.x = silu_f(o.x);
        o.y = silu_f(o.y);
        o.z = silu_f(o.z);
        o.w = silu_f(o.w);

        __stcs(&py[i * C_DV], o);                   // streaming: never re-read
    }
}

extern "C" void kernel_launch(void* const* d_in, const int* in_sizes, int n_in,
                              void* d_out, int out_size) {
    const float4* x  = (const float4*)d_in[0];
    const float4* w4 = (const float4*)d_in[1];
    float4* y = (float4*)d_out;

    const int B = in_sizes[0] / (C_L * C_D);                   // 4
    const long total_threads = (long)B * C_SPB * C_DV;         // 262,144
    const int blocks = (int)(total_threads / 256);             // 1024

    causal_dwconv_silu_kernel<<<blocks, 256>>>(x, w4, y);
}

// round 11
// speedup vs baseline: 1.4798x; 1.0587x over previous
#include <cuda_runtime.h>

// Causal depthwise conv1d (K=4) + SiLU, fp32, (B, L, D), D contiguous.
// R10: wave-quantization fix. R9's 1024 coarse CTAs @3/SM quantize to ~3
// sequential rounds per SM vs 2.31 ideal (~30% tail idle -> DRAM pinned at 68%).
// Now: S=16 spans, 128-thread CTAs, __launch_bounds__(128,6) -> 4096 CTAs,
// ~27.7 CTAs per SM on 6 lanes -> quantization loss ~8%. Same 768 resident
// threads/SM and the same continuous-stream register ring (RING=8, prefetch
// distance 5) so latency coverage is unchanged. Read amp 1.09 -> 1.19.

#define CONV_K 4
#define S      16                    // outputs per thread along L
#define RING   8                     // register ring depth (float4 rows)
#define TPB    128                   // threads per CTA

// Fixed problem shape (reference: B=4, L=4096, D=2048)
#define C_L   4096
#define C_D   2048
#define C_DV  (C_D / 4)              // 512 float4 per row
#define C_SPB (C_L / S)              // 256 spans per (batch, column)

__device__ __forceinline__ float silu_f(float v) {
    return __fdividef(v, 1.0f + __expf(-v));
}

__global__ __launch_bounds__(TPB, 6)
void causal_dwconv_silu_kernel(const float4* __restrict__ x,
                               const float4* __restrict__ w4,
                               float4* __restrict__ y) {
    const unsigned t = blockIdx.x * (unsigned)TPB + threadIdx.x;
    const unsigned dv   = t & (C_DV - 1);           // t % 512
    const unsigned rest = t >> 9;                   // t / 512
    const unsigned sp   = rest & (C_SPB - 1);       // span index within column
    const unsigned b    = rest >> 8;                // rest / 256

    const unsigned l0   = sp * S;
    const unsigned base = b * (C_L * C_DV) + l0 * C_DV + dv;

    const float4* px = x + base;                    // (b, l0, dv); halo at negative offs
    float4*       py = y + base;

    // Weights for channels d = 4*dv + {0..3} (one float4 each).
    const float4 wA = __ldg(&w4[4 * dv + 0]);
    const float4 wB = __ldg(&w4[4 * dv + 1]);
    const float4 wC = __ldg(&w4[4 * dv + 2]);
    const float4 wD = __ldg(&w4[4 * dv + 3]);

    // ---- Prologue: fill ring with rows l0-3 .. l0+4 (front-batched, MLP=8) ----
    float4 v[RING];
    const float4 Z = make_float4(0.f, 0.f, 0.f, 0.f);
    if (l0 == 0) {                                  // warp-uniform branch
        v[0] = Z; v[1] = Z; v[2] = Z;
#pragma unroll
        for (int j = 3; j < RING; ++j) v[j] = __ldg(&px[(j - 3) * C_DV]);
    } else {
#pragma unroll
        for (int j = 0; j < RING; ++j) v[j] = __ldg(&px[(j - 3) * C_DV]);
    }

    // ---- Steady stream: per output, 1 prefetch + 16 FFMA + SiLU + 1 store ----
#pragma unroll
    for (int i = 0; i < S; ++i) {
        const float4 a0 = v[(i + 0) & (RING - 1)];
        const float4 a1 = v[(i + 1) & (RING - 1)];
        const float4 a2 = v[(i + 2) & (RING - 1)];
        const float4 a3 = v[(i + 3) & (RING - 1)];

        if (i + 5 < S) {                            // compile-time predicated
            v[i & (RING - 1)] = __ldg(&px[(i + 5) * C_DV]);
        }

        float4 o;
        o.x = fmaf(a0.x, wA.x, fmaf(a1.x, wA.y, fmaf(a2.x, wA.z, a3.x * wA.w)));
        o.y = fmaf(a0.y, wB.x, fmaf(a1.y, wB.y, fmaf(a2.y, wB.z, a3.y * wB.w)));
        o.z = fmaf(a0.z, wC.x, fmaf(a1.z, wC.y, fmaf(a2.z, wC.z, a3.z * wC.w)));
        o.w = fmaf(a0.w, wD.x, fmaf(a1.w, wD.y, fmaf(a2.w, wD.z, a3.w * wD.w)));

        o.x = silu_f(o.x);
        o.y = silu_f(o.y);
        o.z = silu_f(o.z);
        o.w = silu_f(o.w);

        __stcs(&py[i * C_DV], o);                   // streaming: never re-read
    }
}

extern "C" void kernel_launch(void* const* d_in, const int* in_sizes, int n_in,
                              void* d_out, int out_size) {
    const float4* x  = (const float4*)d_in[0];
    const float4* w4 = (const float4*)d_in[1];
    float4* y = (float4*)d_out;

    const int B = in_sizes[0] / (C_L * C_D);                   // 4
    const long total_threads = (long)B * C_SPB * C_DV;         // 524,288
    const int blocks = (int)(total_threads / TPB);             // 4096

    causal_dwconv_silu_kernel<<<blocks, TPB>>>(x, w4, y);
}